// round 14
// baseline (speedup 1.0000x reference)
#include <cuda_runtime.h>
#include <cuda_fp16.h>
#include <cstdint>
#include <math.h>

#define MTOK 4096      // B*S tokens
#define DMOD 1024
#define SEQ  2048
#define NH   16
#define DK   64
#define NQKV 3072      // fused q|k|v width
#define NQT  16        // q-tiles of 128 rows

// ---------------- scratch (no cudaMalloc allowed) ----------------
__device__ __half g_xh[MTOK * DMOD];
__device__ __half g_qkv[MTOK * NQKV];
__device__ __half g_oh[MTOK * DMOD];
__device__ __half g_wqkv[NQKV * DMOD];   // rows: [Wq(1024) | Wk(1024) | Wv(1024)]
__device__ __half g_wo[DMOD * DMOD];
__device__ float2 g_rtab[SEQ * 32];

static __device__ __forceinline__ float ex2f(float x) {
    float r;
    asm("ex2.approx.f32 %0, %1;" : "=f"(r) : "f"(x));
    return r;
}

// ---------------------------------------------------------------------------
// One prep launch: x->fp16, 4 weights->fp16, rope table.
// ---------------------------------------------------------------------------
#define XN4   (MTOK * DMOD / 4)
#define WN4   (4 * DMOD * DMOD / 4)
#define ROPEN (SEQ * 32)
#define PREP_TOT (XN4 + WN4 + ROPEN)

__global__ void prep_all(const float* __restrict__ x,
                         const float* __restrict__ w0,
                         const float* __restrict__ w1,
                         const float* __restrict__ w2,
                         const float* __restrict__ w3)
{
    int idx = blockIdx.x * blockDim.x + threadIdx.x;
    if (idx < XN4) {
        float4 v = ((const float4*)x)[idx];
        ((__half2*)g_xh)[idx * 2]     = __floats2half2_rn(v.x, v.y);
        ((__half2*)g_xh)[idx * 2 + 1] = __floats2half2_rn(v.z, v.w);
    } else if (idx < XN4 + WN4) {
        int widx = idx - XN4;
        int sel = widx >> 18;
        int off = widx & 0x3FFFF;
        const float* src = sel == 0 ? w0 : sel == 1 ? w1 : sel == 2 ? w2 : w3;
        __half* dst = (sel < 3) ? g_wqkv + (size_t)sel * DMOD * DMOD : g_wo;
        float4 v = ((const float4*)src)[off];
        ((__half2*)dst)[off * 2]     = __floats2half2_rn(v.x, v.y);
        ((__half2*)dst)[off * 2 + 1] = __floats2half2_rn(v.z, v.w);
    } else if (idx < PREP_TOT) {
        int r = idx - XN4 - WN4;
        int p = r >> 5, i = r & 31;
        float freq = (float)exp(-((double)(2 * i) / 64.0) * 9.210340371976184);
        float ang  = (float)p * freq;
        double a = (double)ang;
        const double twopi = 6.283185307179586476925287;
        a -= floor(a / twopi) * twopi;
        float ar = (float)a;
        g_rtab[r] = make_float2(cosf(ar), sinf(ar));
    }
}

// ---------------------------------------------------------------------------
// fp16 HMMA GEMM: CTA 128x128, warp 32x64, BK=64, NEW: 3-stage ring with
// wait_group 1 (two loads in flight; load chain depth 2). stride-72 rows.
// Fused RoPE (cols<2048); q-scale 0.125*log2(e) (log2-domain softmax).
// ---------------------------------------------------------------------------
#define BM 128
#define BN 128
#define BK 64
#define SA 72
#define STAGE_E (BM * SA)
#define HG_SMEM (3 * 2 * STAGE_E * 2)       // 110592 bytes

template <typename OutT, bool DO_ROPE>
__global__ __launch_bounds__(256, 2) void hgemm(
    const __half* __restrict__ A, const __half* __restrict__ B,
    OutT* __restrict__ C, const int* __restrict__ pos,
    int M, int N, int K)
{
    extern __shared__ __half hsm[];
    __half* As = hsm;                       // 3 stages
    __half* Bs = hsm + 3 * STAGE_E;

    const int tid = threadIdx.x;
    const int wid = tid >> 5, lane = tid & 31;
    const int wm = wid & 3, wn = wid >> 2;
    const int m0 = blockIdx.y * BM, n0 = blockIdx.x * BN;
    const int gid = lane >> 2, tg = lane & 3;
    const int ldrow0 = tid >> 3;
    const int ldseg  = tid & 7;

    float acc[2][8][4];
#pragma unroll
    for (int i = 0; i < 2; i++)
#pragma unroll
        for (int j = 0; j < 8; j++)
#pragma unroll
            for (int r = 0; r < 4; r++) acc[i][j][r] = 0.f;

    auto issue_chunk = [&](int c, int st) {
        const __half* ga = A + (size_t)m0 * K + (size_t)c * BK;
        const __half* gb = B + (size_t)n0 * K + (size_t)c * BK;
        __half* sa_base = As + st * STAGE_E;
        __half* sb_base = Bs + st * STAGE_E;
#pragma unroll
        for (int it = 0; it < 4; it++) {
            int row = it * 32 + ldrow0;
            uint32_t sa = (uint32_t)__cvta_generic_to_shared(
                &sa_base[row * SA + ldseg * 8]);
            uint32_t sb = (uint32_t)__cvta_generic_to_shared(
                &sb_base[row * SA + ldseg * 8]);
            const __half* pa = ga + (size_t)row * K + ldseg * 8;
            const __half* pb = gb + (size_t)row * K + ldseg * 8;
            asm volatile("cp.async.cg.shared.global [%0], [%1], 16;"
                         :: "r"(sa), "l"(pa));
            asm volatile("cp.async.cg.shared.global [%0], [%1], 16;"
                         :: "r"(sb), "l"(pb));
        }
        asm volatile("cp.async.commit_group;");
    };

    const int KC = K / BK;                  // 16
    issue_chunk(0, 0);
    issue_chunk(1, 1);

    const int a_row = wm * 32 + (lane & 15);
    const int a_col = (lane & 16) >> 1;
    const int b_row = (lane & 7) + ((lane & 16) >> 1);
    const int b_col = (lane & 8);

    for (int c = 0; c < KC; c++) {
        if (c + 1 < KC) asm volatile("cp.async.wait_group 1;");  // c landed
        else            asm volatile("cp.async.wait_group 0;");
        __syncthreads();   // visibility + all reads of stage (c-1)%3 done
        if (c + 2 < KC) issue_chunk(c + 2, (c + 2) % 3);

        const __half* sa_base = As + (c % 3) * STAGE_E;
        const __half* sb_base = Bs + (c % 3) * STAGE_E;

#pragma unroll
        for (int ks = 0; ks < BK; ks += 16) {
            uint32_t af[2][4];
#pragma unroll
            for (int tm = 0; tm < 2; tm++) {
                uint32_t addr = (uint32_t)__cvta_generic_to_shared(
                    &sa_base[(a_row + tm * 16) * SA + ks + a_col]);
                asm volatile(
                    "ldmatrix.sync.aligned.m8n8.x4.shared.b16 {%0,%1,%2,%3}, [%4];"
                    : "=r"(af[tm][0]), "=r"(af[tm][1]),
                      "=r"(af[tm][2]), "=r"(af[tm][3]) : "r"(addr));
            }
            uint32_t bf[8][2];
#pragma unroll
            for (int np = 0; np < 4; np++) {
                uint32_t addr = (uint32_t)__cvta_generic_to_shared(
                    &sb_base[(wn * 64 + np * 16 + b_row) * SA + ks + b_col]);
                asm volatile(
                    "ldmatrix.sync.aligned.m8n8.x4.shared.b16 {%0,%1,%2,%3}, [%4];"
                    : "=r"(bf[np * 2][0]), "=r"(bf[np * 2][1]),
                      "=r"(bf[np * 2 + 1][0]), "=r"(bf[np * 2 + 1][1])
                    : "r"(addr));
            }
#pragma unroll
            for (int tm = 0; tm < 2; tm++)
#pragma unroll
                for (int tn = 0; tn < 8; tn++) {
                    asm volatile(
                        "mma.sync.aligned.m16n8k16.row.col.f32.f16.f16.f32 "
                        "{%0,%1,%2,%3}, {%4,%5,%6,%7}, {%8,%9}, {%0,%1,%2,%3};"
                        : "+f"(acc[tm][tn][0]), "+f"(acc[tm][tn][1]),
                          "+f"(acc[tm][tn][2]), "+f"(acc[tm][tn][3])
                        : "r"(af[tm][0]), "r"(af[tm][1]),
                          "r"(af[tm][2]), "r"(af[tm][3]),
                          "r"(bf[tn][0]), "r"(bf[tn][1]));
                }
        }
    }

    const bool do_rot = DO_ROPE && (n0 < 2048);
    const float qsc = (DO_ROPE && n0 < 1024) ? 0.125f * 1.4426950408889634f
                                             : 1.0f;
#pragma unroll
    for (int tm = 0; tm < 2; tm++) {
        int rbase = m0 + wm * 32 + tm * 16;
        int r0 = rbase + gid, r1 = rbase + gid + 8;
        int p0 = 0, p1 = 0;
        if (do_rot) { p0 = pos[r0]; p1 = pos[r1]; }
#pragma unroll
        for (int tn = 0; tn < 8; tn++) {
            int col = n0 + wn * 64 + tn * 8 + tg * 2;
            float v00 = acc[tm][tn][0], v01 = acc[tm][tn][1];
            float v10 = acc[tm][tn][2], v11 = acc[tm][tn][3];
            if (do_rot) {
                int i = (col & 63) >> 1;
                float2 c0 = g_rtab[p0 * 32 + i];
                float2 c1 = g_rtab[p1 * 32 + i];
                float t0 = v00 * c0.x - v01 * c0.y;
                v01 = (v00 * c0.y + v01 * c0.x) * qsc; v00 = t0 * qsc;
                float t1 = v10 * c1.x - v11 * c1.y;
                v11 = (v10 * c1.y + v11 * c1.x) * qsc; v10 = t1 * qsc;
            }
            if constexpr (sizeof(OutT) == 4) {
                float* q0 = (float*)C + (size_t)r0 * N + col;
                float* q1 = (float*)C + (size_t)r1 * N + col;
                *(float2*)q0 = make_float2(v00, v01);
                *(float2*)q1 = make_float2(v10, v11);
            } else {
                __half* q0 = (__half*)C + (size_t)r0 * N + col;
                __half* q1 = (__half*)C + (size_t)r1 * N + col;
                *(__half2*)q0 = __floats2half2_rn(v00, v01);
                *(__half2*)q1 = __floats2half2_rn(v10, v11);
            }
        }
    }
}

// ---------------------------------------------------------------------------
// Tensor-core flash attention, causal, log2-domain softmax (R13-verified):
// complementary q-tile pair (bx, 15-bx) per CTA -> one uniform occ-2 wave.
// ---------------------------------------------------------------------------
#define SQH 72
#define KVT (64 * SQH)                                // halves per KV tile
#define ATT_SMEM ((128 * SQH + 6 * KVT) * 2)          // 73728 bytes

__global__ __launch_bounds__(256, 2) void attn_mma(
    const __half* __restrict__ Q, const __half* __restrict__ K,
    const __half* __restrict__ V, __half* __restrict__ O)
{
    extern __shared__ __half sm[];
    __half* Qs = sm;
    __half* Kb = sm + 128 * SQH;                      // 3 stages
    __half* Vb = sm + 128 * SQH + 3 * KVT;            // 3 stages

    const int tid = threadIdx.x;
    const int w = tid >> 5, lane = tid & 31;
    const int gid = lane >> 2, tg = lane & 3;
    const int h = blockIdx.y, b = blockIdx.z;
    const size_t base  = ((size_t)b * SEQ) * NQKV + h * DK;
    const size_t baseO = ((size_t)b * SEQ) * DMOD + h * DK;
    const int lrow = tid >> 3, lseg = tid & 7;
    const int brow = (lane & 7) + ((lane & 16) >> 1);
    const int bcol = (lane & 8);

    auto issue_kv = [&](int kt, int buf) {
#pragma unroll
        for (int it = 0; it < 2; it++) {
            int r = it * 32 + lrow;
            uint32_t dk_ = (uint32_t)__cvta_generic_to_shared(
                &Kb[buf * KVT + r * SQH + lseg * 8]);
            uint32_t dv_ = (uint32_t)__cvta_generic_to_shared(
                &Vb[buf * KVT + r * SQH + lseg * 8]);
            const __half* pk = K + base + (size_t)(kt * 64 + r) * NQKV + lseg * 8;
            const __half* pv = V + base + (size_t)(kt * 64 + r) * NQKV + lseg * 8;
            asm volatile("cp.async.cg.shared.global [%0], [%1], 16;"
                         :: "r"(dk_), "l"(pk));
            asm volatile("cp.async.cg.shared.global [%0], [%1], 16;"
                         :: "r"(dv_), "l"(pv));
        }
        asm volatile("cp.async.commit_group;");
    };

#pragma unroll 1
    for (int half = 0; half < 2; half++) {
        const int qt = half == 0 ? blockIdx.x : (NQT - 1 - blockIdx.x);
        const int qrow0 = qt * 128;
        const int rabs0 = qrow0 + w * 16 + gid;
        const int ktmax = 2 * qt + 1;

#pragma unroll
        for (int it = 0; it < 4; it++) {
            int r = it * 32 + lrow;
            uint32_t dq = (uint32_t)__cvta_generic_to_shared(
                &Qs[r * SQH + lseg * 8]);
            const __half* pq = Q + base + (size_t)(qrow0 + r) * NQKV + lseg * 8;
            asm volatile("cp.async.cg.shared.global [%0], [%1], 16;"
                         :: "r"(dq), "l"(pq));
        }
        issue_kv(0, 0);
        issue_kv(1, 1);                               // ktmax >= 1 always

        asm volatile("cp.async.wait_group 1;");       // Q + KV0 landed
        __syncthreads();

        uint32_t qf[4][4];
#pragma unroll
        for (int ks = 0; ks < 4; ks++) {
            uint32_t addr = (uint32_t)__cvta_generic_to_shared(
                &Qs[(w * 16 + (lane & 15)) * SQH + ks * 16 + ((lane >> 4) << 3)]);
            asm volatile(
                "ldmatrix.sync.aligned.m8n8.x4.shared.b16 {%0,%1,%2,%3}, [%4];"
                : "=r"(qf[ks][0]), "=r"(qf[ks][1]),
                  "=r"(qf[ks][2]), "=r"(qf[ks][3]) : "r"(addr));
        }

        float o[8][4];
        float m0 = -1e30f, m1 = -1e30f, l0 = 0.f, l1 = 0.f;
#pragma unroll
        for (int tn = 0; tn < 8; tn++)
#pragma unroll
            for (int r = 0; r < 4; r++) o[tn][r] = 0.f;

        for (int kt = 0; kt <= ktmax; kt++) {
            if (kt) {
                if (kt < ktmax) asm volatile("cp.async.wait_group 1;");
                else            asm volatile("cp.async.wait_group 0;");
                __syncthreads();
            }
            if (kt + 2 <= ktmax) issue_kv(kt + 2, (kt + 2) % 3);

            if (!(kt == ktmax && w < 4)) {            // skip fully-masked tiles
                const __half* Ks = Kb + (kt % 3) * KVT;
                const __half* Vs = Vb + (kt % 3) * KVT;

                float s[8][4];
#pragma unroll
                for (int tn = 0; tn < 8; tn++)
#pragma unroll
                    for (int r = 0; r < 4; r++) s[tn][r] = 0.f;

#pragma unroll
                for (int ks = 0; ks < 4; ks++) {
                    uint32_t bf[8][2];
#pragma unroll
                    for (int np = 0; np < 4; np++) {
                        uint32_t addr = (uint32_t)__cvta_generic_to_shared(
                            &Ks[(np * 16 + brow) * SQH + ks * 16 + bcol]);
                        asm volatile(
                            "ldmatrix.sync.aligned.m8n8.x4.shared.b16 "
                            "{%0,%1,%2,%3}, [%4];"
                            : "=r"(bf[np * 2][0]), "=r"(bf[np * 2][1]),
                              "=r"(bf[np * 2 + 1][0]), "=r"(bf[np * 2 + 1][1])
                            : "r"(addr));
                    }
#pragma unroll
                    for (int tn = 0; tn < 8; tn++)
                        asm volatile(
                            "mma.sync.aligned.m16n8k16.row.col.f32.f16.f16.f32 "
                            "{%0,%1,%2,%3}, {%4,%5,%6,%7}, {%8,%9}, {%0,%1,%2,%3};"
                            : "+f"(s[tn][0]), "+f"(s[tn][1]),
                              "+f"(s[tn][2]), "+f"(s[tn][3])
                            : "r"(qf[ks][0]), "r"(qf[ks][1]),
                              "r"(qf[ks][2]), "r"(qf[ks][3]),
                              "r"(bf[tn][0]), "r"(bf[tn][1]));
                }

                if (kt >= 2 * qt) {
#pragma unroll
                    for (int tn = 0; tn < 8; tn++) {
                        int cb = kt * 64 + tn * 8 + tg * 2;
                        if (cb     > rabs0)     s[tn][0] = -1e30f;
                        if (cb + 1 > rabs0)     s[tn][1] = -1e30f;
                        if (cb     > rabs0 + 8) s[tn][2] = -1e30f;
                        if (cb + 1 > rabs0 + 8) s[tn][3] = -1e30f;
                    }
                }

                float mx0 = -1e30f, mx1 = -1e30f;
#pragma unroll
                for (int tn = 0; tn < 8; tn++) {
                    mx0 = fmaxf(mx0, fmaxf(s[tn][0], s[tn][1]));
                    mx1 = fmaxf(mx1, fmaxf(s[tn][2], s[tn][3]));
                }
                mx0 = fmaxf(mx0, __shfl_xor_sync(0xffffffffu, mx0, 1));
                mx0 = fmaxf(mx0, __shfl_xor_sync(0xffffffffu, mx0, 2));
                mx1 = fmaxf(mx1, __shfl_xor_sync(0xffffffffu, mx1, 1));
                mx1 = fmaxf(mx1, __shfl_xor_sync(0xffffffffu, mx1, 2));

                float mn0 = fmaxf(m0, mx0), mn1 = fmaxf(m1, mx1);
                float a0 = ex2f(m0 - mn0), a1 = ex2f(m1 - mn1);
                m0 = mn0; m1 = mn1;

                float rs0 = 0.f, rs1 = 0.f;
#pragma unroll
                for (int tn = 0; tn < 8; tn++) {
                    s[tn][0] = ex2f(s[tn][0] - mn0);
                    s[tn][1] = ex2f(s[tn][1] - mn0);
                    s[tn][2] = ex2f(s[tn][2] - mn1);
                    s[tn][3] = ex2f(s[tn][3] - mn1);
                    rs0 += s[tn][0] + s[tn][1];
                    rs1 += s[tn][2] + s[tn][3];
                }
                rs0 += __shfl_xor_sync(0xffffffffu, rs0, 1);
                rs0 += __shfl_xor_sync(0xffffffffu, rs0, 2);
                rs1 += __shfl_xor_sync(0xffffffffu, rs1, 1);
                rs1 += __shfl_xor_sync(0xffffffffu, rs1, 2);
                l0 = l0 * a0 + rs0;
                l1 = l1 * a1 + rs1;

#pragma unroll
                for (int tn = 0; tn < 8; tn++) {
                    o[tn][0] *= a0; o[tn][1] *= a0;
                    o[tn][2] *= a1; o[tn][3] *= a1;
                }

#pragma unroll
                for (int ks = 0; ks < 4; ks++) {
                    uint32_t pf[4];
                    __half2 p0 = __floats2half2_rn(s[2 * ks][0], s[2 * ks][1]);
                    __half2 p1 = __floats2half2_rn(s[2 * ks][2], s[2 * ks][3]);
                    __half2 p2 = __floats2half2_rn(s[2 * ks + 1][0],
                                                   s[2 * ks + 1][1]);
                    __half2 p3 = __floats2half2_rn(s[2 * ks + 1][2],
                                                   s[2 * ks + 1][3]);
                    pf[0] = *(uint32_t*)&p0; pf[1] = *(uint32_t*)&p1;
                    pf[2] = *(uint32_t*)&p2; pf[3] = *(uint32_t*)&p3;

                    uint32_t vb[8][2];
#pragma unroll
                    for (int np = 0; np < 4; np++) {
                        uint32_t addr = (uint32_t)__cvta_generic_to_shared(
                            &Vs[(ks * 16 + (lane & 15)) * SQH + np * 16
                                + ((lane & 16) >> 1)]);
                        asm volatile(
                            "ldmatrix.sync.aligned.m8n8.x4.trans.shared.b16 "
                            "{%0,%1,%2,%3}, [%4];"
                            : "=r"(vb[np * 2][0]), "=r"(vb[np * 2][1]),
                              "=r"(vb[np * 2 + 1][0]), "=r"(vb[np * 2 + 1][1])
                            : "r"(addr));
                    }
#pragma unroll
                    for (int tn = 0; tn < 8; tn++)
                        asm volatile(
                            "mma.sync.aligned.m16n8k16.row.col.f32.f16.f16.f32 "
                            "{%0,%1,%2,%3}, {%4,%5,%6,%7}, {%8,%9}, {%0,%1,%2,%3};"
                            : "+f"(o[tn][0]), "+f"(o[tn][1]),
                              "+f"(o[tn][2]), "+f"(o[tn][3])
                            : "r"(pf[0]), "r"(pf[1]), "r"(pf[2]), "r"(pf[3]),
                              "r"(vb[tn][0]), "r"(vb[tn][1]));
                }
            }
        }

        float i0 = 1.f / l0, i1 = 1.f / l1;
#pragma unroll
        for (int tn = 0; tn < 8; tn++) {
            size_t r0 = baseO + (size_t)(qrow0 + w * 16 + gid) * DMOD
                        + tn * 8 + tg * 2;
            size_t r1 = r0 + 8 * DMOD;
            *(__half2*)(O + r0) = __floats2half2_rn(o[tn][0] * i0,
                                                    o[tn][1] * i0);
            *(__half2*)(O + r1) = __floats2half2_rn(o[tn][2] * i1,
                                                    o[tn][3] * i1);
        }

        __syncthreads();   // all smem reads done before next half reloads
    }
}

// ---------------------------------------------------------------------------
extern "C" void kernel_launch(void* const* d_in, const int* in_sizes, int n_in,
                              void* d_out, int out_size)
{
    const float* x   = (const float*)d_in[0];
    const float* Wq  = (const float*)d_in[1];
    const float* Wk  = (const float*)d_in[2];
    const float* Wv  = (const float*)d_in[3];
    const float* Wo  = (const float*)d_in[4];
    const int*   pos = (const int*)d_in[5];
    float* out = (float*)d_out;

    __half *xh, *qkv, *oh, *wqkv, *wo;
    cudaGetSymbolAddress((void**)&xh,   g_xh);
    cudaGetSymbolAddress((void**)&qkv,  g_qkv);
    cudaGetSymbolAddress((void**)&oh,   g_oh);
    cudaGetSymbolAddress((void**)&wqkv, g_wqkv);
    cudaGetSymbolAddress((void**)&wo,   g_wo);

    cudaFuncSetAttribute(hgemm<__half, true>,
                         cudaFuncAttributeMaxDynamicSharedMemorySize, HG_SMEM);
    cudaFuncSetAttribute(hgemm<float, false>,
                         cudaFuncAttributeMaxDynamicSharedMemorySize, HG_SMEM);
    cudaFuncSetAttribute(attn_mma,
                         cudaFuncAttributeMaxDynamicSharedMemorySize, ATT_SMEM);

    prep_all<<<(PREP_TOT + 255) / 256, 256>>>(x, Wq, Wk, Wv, Wo);

    hgemm<__half, true><<<dim3(NQKV / BN, MTOK / BM), 256, HG_SMEM>>>(
        xh, wqkv, qkv, pos, MTOK, NQKV, DMOD);

    attn_mma<<<dim3(NQT / 2, NH, 2), 256, ATT_SMEM>>>(
        qkv, qkv + 1024, qkv + 2048, oh);

    hgemm<float, false><<<dim3(DMOD / BN, MTOK / BM), 256, HG_SMEM>>>(
        oh, wo, out, nullptr, MTOK, DMOD, DMOD);
}

// round 15
// speedup vs baseline: 1.0207x; 1.0207x over previous
#include <cuda_runtime.h>
#include <cuda_fp16.h>
#include <cstdint>
#include <math.h>

#define MTOK 4096      // B*S tokens
#define DMOD 1024
#define SEQ  2048
#define NH   16
#define DK   64
#define NQKV 3072      // fused q|k|v width
#define NQT  16        // q-tiles of 128 rows

// ---------------- scratch (no cudaMalloc allowed) ----------------
__device__ __half g_xh[MTOK * DMOD];
__device__ __half g_qkv[MTOK * NQKV];
__device__ __half g_oh[MTOK * DMOD];
__device__ __half g_wqkv[NQKV * DMOD];   // rows: [Wq(1024) | Wk(1024) | Wv(1024)]
__device__ __half g_wo[DMOD * DMOD];
__device__ float2 g_rtab[SEQ * 32];

static __device__ __forceinline__ float ex2f(float x) {
    float r;
    asm("ex2.approx.f32 %0, %1;" : "=f"(r) : "f"(x));
    return r;
}

static __device__ __forceinline__ void stg_cs_f2(float* p, float a, float b) {
    asm volatile("st.global.cs.v2.f32 [%0], {%1, %2};"
                 :: "l"(p), "f"(a), "f"(b) : "memory");
}

// ---------------------------------------------------------------------------
// One prep launch: x->fp16, 4 weights->fp16, rope table.
// ---------------------------------------------------------------------------
#define XN4   (MTOK * DMOD / 4)
#define WN4   (4 * DMOD * DMOD / 4)
#define ROPEN (SEQ * 32)
#define PREP_TOT (XN4 + WN4 + ROPEN)

__global__ void prep_all(const float* __restrict__ x,
                         const float* __restrict__ w0,
                         const float* __restrict__ w1,
                         const float* __restrict__ w2,
                         const float* __restrict__ w3)
{
    int idx = blockIdx.x * blockDim.x + threadIdx.x;
    if (idx < XN4) {
        float4 v = ((const float4*)x)[idx];
        ((__half2*)g_xh)[idx * 2]     = __floats2half2_rn(v.x, v.y);
        ((__half2*)g_xh)[idx * 2 + 1] = __floats2half2_rn(v.z, v.w);
    } else if (idx < XN4 + WN4) {
        int widx = idx - XN4;
        int sel = widx >> 18;
        int off = widx & 0x3FFFF;
        const float* src = sel == 0 ? w0 : sel == 1 ? w1 : sel == 2 ? w2 : w3;
        __half* dst = (sel < 3) ? g_wqkv + (size_t)sel * DMOD * DMOD : g_wo;
        float4 v = ((const float4*)src)[off];
        ((__half2*)dst)[off * 2]     = __floats2half2_rn(v.x, v.y);
        ((__half2*)dst)[off * 2 + 1] = __floats2half2_rn(v.z, v.w);
    } else if (idx < PREP_TOT) {
        int r = idx - XN4 - WN4;
        int p = r >> 5, i = r & 31;
        float freq = (float)exp(-((double)(2 * i) / 64.0) * 9.210340371976184);
        float ang  = (float)p * freq;
        double a = (double)ang;
        const double twopi = 6.283185307179586476925287;
        a -= floor(a / twopi) * twopi;
        float ar = (float)a;
        g_rtab[r] = make_float2(cosf(ar), sinf(ar));
    }
}

// ---------------------------------------------------------------------------
// fp16 HMMA GEMM (R13-verified, reverted): CTA 128x128, warp 32x64, BK=64,
// 2-stage ring, stride-72 rows. Fused RoPE (cols<2048); q-scale
// 0.125*log2(e) (log2-domain softmax). fp32 output via streaming stores.
// ---------------------------------------------------------------------------
#define BM 128
#define BN 128
#define BK 64
#define SA 72
#define STAGE_E (BM * SA)
#define HG_SMEM (2 * 2 * STAGE_E * 2)       // 73728 bytes

template <typename OutT, bool DO_ROPE>
__global__ __launch_bounds__(256, 2) void hgemm(
    const __half* __restrict__ A, const __half* __restrict__ B,
    OutT* __restrict__ C, const int* __restrict__ pos,
    int M, int N, int K)
{
    extern __shared__ __half hsm[];
    __half* As = hsm;
    __half* Bs = hsm + 2 * STAGE_E;

    const int tid = threadIdx.x;
    const int wid = tid >> 5, lane = tid & 31;
    const int wm = wid & 3, wn = wid >> 2;
    const int m0 = blockIdx.y * BM, n0 = blockIdx.x * BN;
    const int gid = lane >> 2, tg = lane & 3;
    const int ldrow0 = tid >> 3;
    const int ldseg  = tid & 7;

    float acc[2][8][4];
#pragma unroll
    for (int i = 0; i < 2; i++)
#pragma unroll
        for (int j = 0; j < 8; j++)
#pragma unroll
            for (int r = 0; r < 4; r++) acc[i][j][r] = 0.f;

    auto issue_chunk = [&](int c, int buf) {
        const __half* ga = A + (size_t)m0 * K + (size_t)c * BK;
        const __half* gb = B + (size_t)n0 * K + (size_t)c * BK;
        __half* sa_base = As + buf * STAGE_E;
        __half* sb_base = Bs + buf * STAGE_E;
#pragma unroll
        for (int it = 0; it < 4; it++) {
            int row = it * 32 + ldrow0;
            uint32_t sa = (uint32_t)__cvta_generic_to_shared(
                &sa_base[row * SA + ldseg * 8]);
            uint32_t sb = (uint32_t)__cvta_generic_to_shared(
                &sb_base[row * SA + ldseg * 8]);
            const __half* pa = ga + (size_t)row * K + ldseg * 8;
            const __half* pb = gb + (size_t)row * K + ldseg * 8;
            asm volatile("cp.async.cg.shared.global [%0], [%1], 16;"
                         :: "r"(sa), "l"(pa));
            asm volatile("cp.async.cg.shared.global [%0], [%1], 16;"
                         :: "r"(sb), "l"(pb));
        }
        asm volatile("cp.async.commit_group;");
    };

    const int KC = K / BK;                  // 16
    issue_chunk(0, 0);

    const int a_row = wm * 32 + (lane & 15);
    const int a_col = (lane & 16) >> 1;
    const int b_row = (lane & 7) + ((lane & 16) >> 1);
    const int b_col = (lane & 8);

    for (int c = 0; c < KC; c++) {
        asm volatile("cp.async.wait_group 0;");   // chunk c landed
        __syncthreads();   // + all warps done reading the other stage
        if (c + 1 < KC) issue_chunk(c + 1, (c + 1) & 1);

        const __half* sa_base = As + (c & 1) * STAGE_E;
        const __half* sb_base = Bs + (c & 1) * STAGE_E;

#pragma unroll
        for (int ks = 0; ks < BK; ks += 16) {
            uint32_t af[2][4];
#pragma unroll
            for (int tm = 0; tm < 2; tm++) {
                uint32_t addr = (uint32_t)__cvta_generic_to_shared(
                    &sa_base[(a_row + tm * 16) * SA + ks + a_col]);
                asm volatile(
                    "ldmatrix.sync.aligned.m8n8.x4.shared.b16 {%0,%1,%2,%3}, [%4];"
                    : "=r"(af[tm][0]), "=r"(af[tm][1]),
                      "=r"(af[tm][2]), "=r"(af[tm][3]) : "r"(addr));
            }
            uint32_t bf[8][2];
#pragma unroll
            for (int np = 0; np < 4; np++) {
                uint32_t addr = (uint32_t)__cvta_generic_to_shared(
                    &sb_base[(wn * 64 + np * 16 + b_row) * SA + ks + b_col]);
                asm volatile(
                    "ldmatrix.sync.aligned.m8n8.x4.shared.b16 {%0,%1,%2,%3}, [%4];"
                    : "=r"(bf[np * 2][0]), "=r"(bf[np * 2][1]),
                      "=r"(bf[np * 2 + 1][0]), "=r"(bf[np * 2 + 1][1])
                    : "r"(addr));
            }
#pragma unroll
            for (int tm = 0; tm < 2; tm++)
#pragma unroll
                for (int tn = 0; tn < 8; tn++) {
                    asm volatile(
                        "mma.sync.aligned.m16n8k16.row.col.f32.f16.f16.f32 "
                        "{%0,%1,%2,%3}, {%4,%5,%6,%7}, {%8,%9}, {%0,%1,%2,%3};"
                        : "+f"(acc[tm][tn][0]), "+f"(acc[tm][tn][1]),
                          "+f"(acc[tm][tn][2]), "+f"(acc[tm][tn][3])
                        : "r"(af[tm][0]), "r"(af[tm][1]),
                          "r"(af[tm][2]), "r"(af[tm][3]),
                          "r"(bf[tn][0]), "r"(bf[tn][1]));
                }
        }
    }

    const bool do_rot = DO_ROPE && (n0 < 2048);
    const float qsc = (DO_ROPE && n0 < 1024) ? 0.125f * 1.4426950408889634f
                                             : 1.0f;
#pragma unroll
    for (int tm = 0; tm < 2; tm++) {
        int rbase = m0 + wm * 32 + tm * 16;
        int r0 = rbase + gid, r1 = rbase + gid + 8;
        int p0 = 0, p1 = 0;
        if (do_rot) { p0 = pos[r0]; p1 = pos[r1]; }
#pragma unroll
        for (int tn = 0; tn < 8; tn++) {
            int col = n0 + wn * 64 + tn * 8 + tg * 2;
            float v00 = acc[tm][tn][0], v01 = acc[tm][tn][1];
            float v10 = acc[tm][tn][2], v11 = acc[tm][tn][3];
            if (do_rot) {
                int i = (col & 63) >> 1;
                float2 c0 = g_rtab[p0 * 32 + i];
                float2 c1 = g_rtab[p1 * 32 + i];
                float t0 = v00 * c0.x - v01 * c0.y;
                v01 = (v00 * c0.y + v01 * c0.x) * qsc; v00 = t0 * qsc;
                float t1 = v10 * c1.x - v11 * c1.y;
                v11 = (v10 * c1.y + v11 * c1.x) * qsc; v10 = t1 * qsc;
            }
            if constexpr (sizeof(OutT) == 4) {
                // final output: write-once, never re-read -> streaming stores
                stg_cs_f2((float*)C + (size_t)r0 * N + col, v00, v01);
                stg_cs_f2((float*)C + (size_t)r1 * N + col, v10, v11);
            } else {
                __half* q0 = (__half*)C + (size_t)r0 * N + col;
                __half* q1 = (__half*)C + (size_t)r1 * N + col;
                *(__half2*)q0 = __floats2half2_rn(v00, v01);
                *(__half2*)q1 = __floats2half2_rn(v10, v11);
            }
        }
    }
}

// ---------------------------------------------------------------------------
// Tensor-core flash attention, causal, log2-domain softmax (R13-verified):
// complementary q-tile pair (bx, 15-bx) per CTA -> one uniform occ-2 wave.
// ---------------------------------------------------------------------------
#define SQH 72
#define KVT (64 * SQH)                                // halves per KV tile
#define ATT_SMEM ((128 * SQH + 6 * KVT) * 2)          // 73728 bytes

__global__ __launch_bounds__(256, 2) void attn_mma(
    const __half* __restrict__ Q, const __half* __restrict__ K,
    const __half* __restrict__ V, __half* __restrict__ O)
{
    extern __shared__ __half sm[];
    __half* Qs = sm;
    __half* Kb = sm + 128 * SQH;                      // 3 stages
    __half* Vb = sm + 128 * SQH + 3 * KVT;            // 3 stages

    const int tid = threadIdx.x;
    const int w = tid >> 5, lane = tid & 31;
    const int gid = lane >> 2, tg = lane & 3;
    const int h = blockIdx.y, b = blockIdx.z;
    const size_t base  = ((size_t)b * SEQ) * NQKV + h * DK;
    const size_t baseO = ((size_t)b * SEQ) * DMOD + h * DK;
    const int lrow = tid >> 3, lseg = tid & 7;
    const int brow = (lane & 7) + ((lane & 16) >> 1);
    const int bcol = (lane & 8);

    auto issue_kv = [&](int kt, int buf) {
#pragma unroll
        for (int it = 0; it < 2; it++) {
            int r = it * 32 + lrow;
            uint32_t dk_ = (uint32_t)__cvta_generic_to_shared(
                &Kb[buf * KVT + r * SQH + lseg * 8]);
            uint32_t dv_ = (uint32_t)__cvta_generic_to_shared(
                &Vb[buf * KVT + r * SQH + lseg * 8]);
            const __half* pk = K + base + (size_t)(kt * 64 + r) * NQKV + lseg * 8;
            const __half* pv = V + base + (size_t)(kt * 64 + r) * NQKV + lseg * 8;
            asm volatile("cp.async.cg.shared.global [%0], [%1], 16;"
                         :: "r"(dk_), "l"(pk));
            asm volatile("cp.async.cg.shared.global [%0], [%1], 16;"
                         :: "r"(dv_), "l"(pv));
        }
        asm volatile("cp.async.commit_group;");
    };

#pragma unroll 1
    for (int half = 0; half < 2; half++) {
        const int qt = half == 0 ? blockIdx.x : (NQT - 1 - blockIdx.x);
        const int qrow0 = qt * 128;
        const int rabs0 = qrow0 + w * 16 + gid;
        const int ktmax = 2 * qt + 1;

#pragma unroll
        for (int it = 0; it < 4; it++) {
            int r = it * 32 + lrow;
            uint32_t dq = (uint32_t)__cvta_generic_to_shared(
                &Qs[r * SQH + lseg * 8]);
            const __half* pq = Q + base + (size_t)(qrow0 + r) * NQKV + lseg * 8;
            asm volatile("cp.async.cg.shared.global [%0], [%1], 16;"
                         :: "r"(dq), "l"(pq));
        }
        issue_kv(0, 0);
        issue_kv(1, 1);                               // ktmax >= 1 always

        asm volatile("cp.async.wait_group 1;");       // Q + KV0 landed
        __syncthreads();

        uint32_t qf[4][4];
#pragma unroll
        for (int ks = 0; ks < 4; ks++) {
            uint32_t addr = (uint32_t)__cvta_generic_to_shared(
                &Qs[(w * 16 + (lane & 15)) * SQH + ks * 16 + ((lane >> 4) << 3)]);
            asm volatile(
                "ldmatrix.sync.aligned.m8n8.x4.shared.b16 {%0,%1,%2,%3}, [%4];"
                : "=r"(qf[ks][0]), "=r"(qf[ks][1]),
                  "=r"(qf[ks][2]), "=r"(qf[ks][3]) : "r"(addr));
        }

        float o[8][4];
        float m0 = -1e30f, m1 = -1e30f, l0 = 0.f, l1 = 0.f;
#pragma unroll
        for (int tn = 0; tn < 8; tn++)
#pragma unroll
            for (int r = 0; r < 4; r++) o[tn][r] = 0.f;

        for (int kt = 0; kt <= ktmax; kt++) {
            if (kt) {
                if (kt < ktmax) asm volatile("cp.async.wait_group 1;");
                else            asm volatile("cp.async.wait_group 0;");
                __syncthreads();
            }
            if (kt + 2 <= ktmax) issue_kv(kt + 2, (kt + 2) % 3);

            if (!(kt == ktmax && w < 4)) {            // skip fully-masked tiles
                const __half* Ks = Kb + (kt % 3) * KVT;
                const __half* Vs = Vb + (kt % 3) * KVT;

                float s[8][4];
#pragma unroll
                for (int tn = 0; tn < 8; tn++)
#pragma unroll
                    for (int r = 0; r < 4; r++) s[tn][r] = 0.f;

#pragma unroll
                for (int ks = 0; ks < 4; ks++) {
                    uint32_t bf[8][2];
#pragma unroll
                    for (int np = 0; np < 4; np++) {
                        uint32_t addr = (uint32_t)__cvta_generic_to_shared(
                            &Ks[(np * 16 + brow) * SQH + ks * 16 + bcol]);
                        asm volatile(
                            "ldmatrix.sync.aligned.m8n8.x4.shared.b16 "
                            "{%0,%1,%2,%3}, [%4];"
                            : "=r"(bf[np * 2][0]), "=r"(bf[np * 2][1]),
                              "=r"(bf[np * 2 + 1][0]), "=r"(bf[np * 2 + 1][1])
                            : "r"(addr));
                    }
#pragma unroll
                    for (int tn = 0; tn < 8; tn++)
                        asm volatile(
                            "mma.sync.aligned.m16n8k16.row.col.f32.f16.f16.f32 "
                            "{%0,%1,%2,%3}, {%4,%5,%6,%7}, {%8,%9}, {%0,%1,%2,%3};"
                            : "+f"(s[tn][0]), "+f"(s[tn][1]),
                              "+f"(s[tn][2]), "+f"(s[tn][3])
                            : "r"(qf[ks][0]), "r"(qf[ks][1]),
                              "r"(qf[ks][2]), "r"(qf[ks][3]),
                              "r"(bf[tn][0]), "r"(bf[tn][1]));
                }

                if (kt >= 2 * qt) {
#pragma unroll
                    for (int tn = 0; tn < 8; tn++) {
                        int cb = kt * 64 + tn * 8 + tg * 2;
                        if (cb     > rabs0)     s[tn][0] = -1e30f;
                        if (cb + 1 > rabs0)     s[tn][1] = -1e30f;
                        if (cb     > rabs0 + 8) s[tn][2] = -1e30f;
                        if (cb + 1 > rabs0 + 8) s[tn][3] = -1e30f;
                    }
                }

                float mx0 = -1e30f, mx1 = -1e30f;
#pragma unroll
                for (int tn = 0; tn < 8; tn++) {
                    mx0 = fmaxf(mx0, fmaxf(s[tn][0], s[tn][1]));
                    mx1 = fmaxf(mx1, fmaxf(s[tn][2], s[tn][3]));
                }
                mx0 = fmaxf(mx0, __shfl_xor_sync(0xffffffffu, mx0, 1));
                mx0 = fmaxf(mx0, __shfl_xor_sync(0xffffffffu, mx0, 2));
                mx1 = fmaxf(mx1, __shfl_xor_sync(0xffffffffu, mx1, 1));
                mx1 = fmaxf(mx1, __shfl_xor_sync(0xffffffffu, mx1, 2));

                float mn0 = fmaxf(m0, mx0), mn1 = fmaxf(m1, mx1);
                float a0 = ex2f(m0 - mn0), a1 = ex2f(m1 - mn1);
                m0 = mn0; m1 = mn1;

                float rs0 = 0.f, rs1 = 0.f;
#pragma unroll
                for (int tn = 0; tn < 8; tn++) {
                    s[tn][0] = ex2f(s[tn][0] - mn0);
                    s[tn][1] = ex2f(s[tn][1] - mn0);
                    s[tn][2] = ex2f(s[tn][2] - mn1);
                    s[tn][3] = ex2f(s[tn][3] - mn1);
                    rs0 += s[tn][0] + s[tn][1];
                    rs1 += s[tn][2] + s[tn][3];
                }
                rs0 += __shfl_xor_sync(0xffffffffu, rs0, 1);
                rs0 += __shfl_xor_sync(0xffffffffu, rs0, 2);
                rs1 += __shfl_xor_sync(0xffffffffu, rs1, 1);
                rs1 += __shfl_xor_sync(0xffffffffu, rs1, 2);
                l0 = l0 * a0 + rs0;
                l1 = l1 * a1 + rs1;

#pragma unroll
                for (int tn = 0; tn < 8; tn++) {
                    o[tn][0] *= a0; o[tn][1] *= a0;
                    o[tn][2] *= a1; o[tn][3] *= a1;
                }

#pragma unroll
                for (int ks = 0; ks < 4; ks++) {
                    uint32_t pf[4];
                    __half2 p0 = __floats2half2_rn(s[2 * ks][0], s[2 * ks][1]);
                    __half2 p1 = __floats2half2_rn(s[2 * ks][2], s[2 * ks][3]);
                    __half2 p2 = __floats2half2_rn(s[2 * ks + 1][0],
                                                   s[2 * ks + 1][1]);
                    __half2 p3 = __floats2half2_rn(s[2 * ks + 1][2],
                                                   s[2 * ks + 1][3]);
                    pf[0] = *(uint32_t*)&p0; pf[1] = *(uint32_t*)&p1;
                    pf[2] = *(uint32_t*)&p2; pf[3] = *(uint32_t*)&p3;

                    uint32_t vb[8][2];
#pragma unroll
                    for (int np = 0; np < 4; np++) {
                        uint32_t addr = (uint32_t)__cvta_generic_to_shared(
                            &Vs[(ks * 16 + (lane & 15)) * SQH + np * 16
                                + ((lane & 16) >> 1)]);
                        asm volatile(
                            "ldmatrix.sync.aligned.m8n8.x4.trans.shared.b16 "
                            "{%0,%1,%2,%3}, [%4];"
                            : "=r"(vb[np * 2][0]), "=r"(vb[np * 2][1]),
                              "=r"(vb[np * 2 + 1][0]), "=r"(vb[np * 2 + 1][1])
                            : "r"(addr));
                    }
#pragma unroll
                    for (int tn = 0; tn < 8; tn++)
                        asm volatile(
                            "mma.sync.aligned.m16n8k16.row.col.f32.f16.f16.f32 "
                            "{%0,%1,%2,%3}, {%4,%5,%6,%7}, {%8,%9}, {%0,%1,%2,%3};"
                            : "+f"(o[tn][0]), "+f"(o[tn][1]),
                              "+f"(o[tn][2]), "+f"(o[tn][3])
                            : "r"(pf[0]), "r"(pf[1]), "r"(pf[2]), "r"(pf[3]),
                              "r"(vb[tn][0]), "r"(vb[tn][1]));
                }
            }
        }

        float i0 = 1.f / l0, i1 = 1.f / l1;
#pragma unroll
        for (int tn = 0; tn < 8; tn++) {
            size_t r0 = baseO + (size_t)(qrow0 + w * 16 + gid) * DMOD
                        + tn * 8 + tg * 2;
            size_t r1 = r0 + 8 * DMOD;
            *(__half2*)(O + r0) = __floats2half2_rn(o[tn][0] * i0,
                                                    o[tn][1] * i0);
            *(__half2*)(O + r1) = __floats2half2_rn(o[tn][2] * i1,
                                                    o[tn][3] * i1);
        }

        __syncthreads();   // all smem reads done before next half reloads
    }
}

// ---------------------------------------------------------------------------
extern "C" void kernel_launch(void* const* d_in, const int* in_sizes, int n_in,
                              void* d_out, int out_size)
{
    const float* x   = (const float*)d_in[0];
    const float* Wq  = (const float*)d_in[1];
    const float* Wk  = (const float*)d_in[2];
    const float* Wv  = (const float*)d_in[3];
    const float* Wo  = (const float*)d_in[4];
    const int*   pos = (const int*)d_in[5];
    float* out = (float*)d_out;

    __half *xh, *qkv, *oh, *wqkv, *wo;
    cudaGetSymbolAddress((void**)&xh,   g_xh);
    cudaGetSymbolAddress((void**)&qkv,  g_qkv);
    cudaGetSymbolAddress((void**)&oh,   g_oh);
    cudaGetSymbolAddress((void**)&wqkv, g_wqkv);
    cudaGetSymbolAddress((void**)&wo,   g_wo);

    cudaFuncSetAttribute(hgemm<__half, true>,
                         cudaFuncAttributeMaxDynamicSharedMemorySize, HG_SMEM);
    cudaFuncSetAttribute(hgemm<float, false>,
                         cudaFuncAttributeMaxDynamicSharedMemorySize, HG_SMEM);
    cudaFuncSetAttribute(attn_mma,
                         cudaFuncAttributeMaxDynamicSharedMemorySize, ATT_SMEM);

    prep_all<<<(PREP_TOT + 255) / 256, 256>>>(x, Wq, Wk, Wv, Wo);

    hgemm<__half, true><<<dim3(NQKV / BN, MTOK / BM), 256, HG_SMEM>>>(
        xh, wqkv, qkv, pos, MTOK, NQKV, DMOD);

    attn_mma<<<dim3(NQT / 2, NH, 2), 256, ATT_SMEM>>>(
        qkv, qkv + 1024, qkv + 2048, oh);

    hgemm<float, false><<<dim3(DMOD / BN, MTOK / BM), 256, HG_SMEM>>>(
        oh, wo, out, nullptr, MTOK, DMOD, DMOD);
}